// round 1
// baseline (speedup 1.0000x reference)
#include <cuda_runtime.h>
#include <math.h>

#define S_FR   16
#define P_TOK  512
#define C_DIM  768
#define H_HEADS 12
#define K_COV  6
#define D_DIM  64
#define N_TOK  8192
#define QKV_N  2304

// Scratch (allocation-free: __device__ globals)
__device__ float g_q[H_HEADS * N_TOK * D_DIM];
__device__ float g_k[H_HEADS * N_TOK * D_DIM];
__device__ float g_v[H_HEADS * N_TOK * D_DIM];
__device__ float g_attn[N_TOK * C_DIM];

// ---------------------------------------------------------------------------
// Tiled fp32 GEMM: C[M,Ncols] = A[M,768] * B[768,Ncols] + bias
// MODE 0: scatter into q/k/v [H,N,D];  MODE 1: A := g_attn, write d_out
// BM=BN=128, BK=16, 256 threads, 8x8 microtile.
// ---------------------------------------------------------------------------
template <int MODE>
__global__ __launch_bounds__(256) void gemm_kernel(
    const float* __restrict__ A, const float* __restrict__ B,
    const float* __restrict__ bias, float* __restrict__ Cout, int Ncols) {
  constexpr int BM = 128, BN = 128, BK = 16, TM = 8, TN = 8;
  __shared__ float As[BK][BM + 4];   // transposed A tile, padded
  __shared__ float Bs[BK][BN];
  const int K = C_DIM;
  const int bn = blockIdx.x, bm = blockIdx.y;
  const int tid = threadIdx.x;
  const int tr = tid >> 4, tc = tid & 15;

  const float* Ap = (MODE == 1) ? (const float*)g_attn : A;

  float acc[TM][TN];
#pragma unroll
  for (int i = 0; i < TM; i++)
#pragma unroll
    for (int j = 0; j < TN; j++) acc[i][j] = 0.f;

  const int arow = tid >> 2;          // 0..63
  const int acol = (tid & 3) << 2;    // 0,4,8,12
  const int brow = tid >> 5;          // 0..7
  const int bcol = (tid & 31) << 2;   // 0..124

  const float* Ab = Ap + (size_t)(bm * BM) * K;
  const float* Bb = B + bn * BN;

  for (int k0 = 0; k0 < K; k0 += BK) {
#pragma unroll
    for (int i = 0; i < BM; i += 64) {
      float4 a = *(const float4*)&Ab[(size_t)(arow + i) * K + k0 + acol];
      As[acol + 0][arow + i] = a.x;
      As[acol + 1][arow + i] = a.y;
      As[acol + 2][arow + i] = a.z;
      As[acol + 3][arow + i] = a.w;
    }
#pragma unroll
    for (int i = 0; i < BK; i += 8) {
      *(float4*)&Bs[brow + i][bcol] =
          *(const float4*)&Bb[(size_t)(k0 + brow + i) * Ncols + bcol];
    }
    __syncthreads();
#pragma unroll
    for (int kk = 0; kk < BK; kk++) {
      float a[TM], b[TN];
      *(float4*)&a[0] = *(float4*)&As[kk][tr * TM + 0];
      *(float4*)&a[4] = *(float4*)&As[kk][tr * TM + 4];
      *(float4*)&b[0] = *(float4*)&Bs[kk][tc * TN + 0];
      *(float4*)&b[4] = *(float4*)&Bs[kk][tc * TN + 4];
#pragma unroll
      for (int i = 0; i < TM; i++)
#pragma unroll
        for (int j = 0; j < TN; j++) acc[i][j] = fmaf(a[i], b[j], acc[i][j]);
    }
    __syncthreads();
  }

#pragma unroll
  for (int i = 0; i < TM; i++) {
    const int row = bm * BM + tr * TM + i;
#pragma unroll
    for (int j = 0; j < TN; j++) {
      const int col = bn * BN + tc * TN + j;
      float v = acc[i][j] + bias[col];
      if (MODE == 0) {
        const int which = col / C_DIM;          // uniform per block (768 = 6*128)
        const int rem = col - which * C_DIM;
        const int h = rem >> 6, d = rem & 63;
        float* dst = (which == 0) ? g_q : (which == 1 ? g_k : g_v);
        dst[((size_t)h * N_TOK + row) * D_DIM + d] = v;
      } else {
        Cout[(size_t)row * C_DIM + col] = v;
      }
    }
  }
}

// ---------------------------------------------------------------------------
// Flash-style fp32 attention. One block = (frame f, head h, 64-query tile).
// Streams 48 key tiles of 64 (6 covisible frames x 512 tokens).
// smem: Qt[64][64] (d-major), Kt[64][64] (d-major), Vs[64][64] (key-major),
//       Ps[64][68] scores, m/l/r row stats.
// ---------------------------------------------------------------------------
#define PSTR 68
#define ATTN_SMEM (3 * 64 * 64 * 4 + 64 * PSTR * 4 + 3 * 64 * 4)

__global__ __launch_bounds__(256) void attn_kernel(const int* __restrict__ covis) {
  extern __shared__ float sm[];
  float* Qt = sm;                  // 64*64
  float* Kt = Qt + 64 * 64;        // 64*64
  float* Vs = Kt + 64 * 64;        // 64*64
  float* Ps = Vs + 64 * 64;        // 64*PSTR
  float* m_s = Ps + 64 * PSTR;
  float* l_s = m_s + 64;
  float* r_s = l_s + 64;

  const int tid = threadIdx.x;
  const int qt = blockIdx.x, h = blockIdx.y, f = blockIdx.z;

  const float* qptr = g_q + ((size_t)h * N_TOK + f * P_TOK + qt * 64) * D_DIM;
  {
    const int r = tid >> 4, c4 = (tid & 15) << 2;
#pragma unroll
    for (int i = 0; i < 64; i += 16) {
      float4 qv = *(const float4*)&qptr[(r + i) * D_DIM + c4];
      Qt[(c4 + 0) * 64 + r + i] = qv.x;
      Qt[(c4 + 1) * 64 + r + i] = qv.y;
      Qt[(c4 + 2) * 64 + r + i] = qv.z;
      Qt[(c4 + 3) * 64 + r + i] = qv.w;
    }
  }
  if (tid < 64) { m_s[tid] = -INFINITY; l_s[tid] = 0.f; }

  const int tq = tid >> 4, tc = tid & 15;
  float acc[4][4];
#pragma unroll
  for (int i = 0; i < 4; i++)
#pragma unroll
    for (int j = 0; j < 4; j++) acc[i][j] = 0.f;

  const float scale = 0.125f;  // 64^-0.5

  for (int t = 0; t < (K_COV * P_TOK) / 64; t++) {   // 48 key tiles
    const int frame = covis[f * K_COV + (t >> 3)];
    const int off = (t & 7) << 6;
    const float* kptr = g_k + ((size_t)h * N_TOK + frame * P_TOK + off) * D_DIM;
    const float* vptr = g_v + ((size_t)h * N_TOK + frame * P_TOK + off) * D_DIM;

    __syncthreads();  // previous PV done (also covers Qt/m_s init on iter 0)
    {
      const int r = tid >> 4, c4 = (tid & 15) << 2;
#pragma unroll
      for (int i = 0; i < 64; i += 16) {
        float4 kv = *(const float4*)&kptr[(r + i) * D_DIM + c4];
        Kt[(c4 + 0) * 64 + r + i] = kv.x;
        Kt[(c4 + 1) * 64 + r + i] = kv.y;
        Kt[(c4 + 2) * 64 + r + i] = kv.z;
        Kt[(c4 + 3) * 64 + r + i] = kv.w;
        *(float4*)&Vs[(r + i) * 64 + c4] =
            *(const float4*)&vptr[(r + i) * D_DIM + c4];
      }
    }
    __syncthreads();

    // S = Q K^T (4x4 microtile per thread)
    float s[4][4];
#pragma unroll
    for (int i = 0; i < 4; i++)
#pragma unroll
      for (int j = 0; j < 4; j++) s[i][j] = 0.f;
#pragma unroll
    for (int d = 0; d < 64; d++) {
      float a[4], b[4];
      *(float4*)a = *(float4*)&Qt[d * 64 + tq * 4];
      *(float4*)b = *(float4*)&Kt[d * 64 + tc * 4];
#pragma unroll
      for (int i = 0; i < 4; i++)
#pragma unroll
        for (int j = 0; j < 4; j++) s[i][j] = fmaf(a[i], b[j], s[i][j]);
    }
#pragma unroll
    for (int i = 0; i < 4; i++)
#pragma unroll
      for (int j = 0; j < 4; j++)
        Ps[(tq * 4 + i) * PSTR + tc * 4 + j] = s[i][j] * scale;
    __syncthreads();

    // Online softmax: 4 threads per query row (shfl reductions within the quad)
    {
      const int row = tid >> 2, qu = tid & 3;
      float* prow = Ps + row * PSTR + qu * 16;
      float mx = -INFINITY;
#pragma unroll
      for (int k2 = 0; k2 < 16; k2++) mx = fmaxf(mx, prow[k2]);
      mx = fmaxf(mx, __shfl_xor_sync(0xffffffffu, mx, 1));
      mx = fmaxf(mx, __shfl_xor_sync(0xffffffffu, mx, 2));
      const float m_old = m_s[row];
      const float m_new = fmaxf(m_old, mx);
      float r = (m_old == -INFINITY) ? 0.f : __expf(m_old - m_new);
      float sum = 0.f;
#pragma unroll
      for (int k2 = 0; k2 < 16; k2++) {
        float e = __expf(prow[k2] - m_new);
        prow[k2] = e;
        sum += e;
      }
      sum += __shfl_xor_sync(0xffffffffu, sum, 1);
      sum += __shfl_xor_sync(0xffffffffu, sum, 2);
      if (qu == 0) {
        r_s[row] = r;
        l_s[row] = l_s[row] * r + sum;
        m_s[row] = m_new;
      }
    }
    __syncthreads();

    // Rescale O and accumulate P*V
    float rr[4];
#pragma unroll
    for (int i = 0; i < 4; i++) rr[i] = r_s[tq * 4 + i];
#pragma unroll
    for (int i = 0; i < 4; i++)
#pragma unroll
      for (int j = 0; j < 4; j++) acc[i][j] *= rr[i];

#pragma unroll
    for (int k4 = 0; k4 < 64; k4 += 4) {
      float a4[4][4];
#pragma unroll
      for (int i = 0; i < 4; i++)
        *(float4*)a4[i] = *(float4*)&Ps[(tq * 4 + i) * PSTR + k4];
#pragma unroll
      for (int u = 0; u < 4; u++) {
        float b[4];
        *(float4*)b = *(float4*)&Vs[(k4 + u) * 64 + tc * 4];
#pragma unroll
        for (int i = 0; i < 4; i++)
#pragma unroll
          for (int j = 0; j < 4; j++)
            acc[i][j] = fmaf(a4[i][u], b[j], acc[i][j]);
      }
    }
  }

  // Finalize: divide by l, write [N, H*D]
  float* optr = g_attn + ((size_t)(f * P_TOK + qt * 64)) * C_DIM + h * D_DIM;
#pragma unroll
  for (int i = 0; i < 4; i++) {
    const float inv = 1.f / l_s[tq * 4 + i];
    float4 o;
    o.x = acc[i][0] * inv;
    o.y = acc[i][1] * inv;
    o.z = acc[i][2] * inv;
    o.w = acc[i][3] * inv;
    *(float4*)&optr[(tq * 4 + i) * C_DIM + tc * 4] = o;
  }
}

// ---------------------------------------------------------------------------
extern "C" void kernel_launch(void* const* d_in, const int* in_sizes, int n_in,
                              void* d_out, int out_size) {
  const float* x     = (const float*)d_in[0];
  const float* Wqkv  = (const float*)d_in[1];
  const float* bqkv  = (const float*)d_in[2];
  const float* Wproj = (const float*)d_in[3];
  const float* bproj = (const float*)d_in[4];
  const int*   covis = (const int*)d_in[5];
  float* out = (float*)d_out;
  (void)in_sizes; (void)n_in; (void)out_size;

  cudaFuncSetAttribute(attn_kernel, cudaFuncAttributeMaxDynamicSharedMemorySize,
                       ATTN_SMEM);

  gemm_kernel<0><<<dim3(QKV_N / 128, N_TOK / 128), 256>>>(x, Wqkv, bqkv,
                                                          nullptr, QKV_N);
  attn_kernel<<<dim3(P_TOK / 64, H_HEADS, S_FR), 256, ATTN_SMEM>>>(covis);
  gemm_kernel<1><<<dim3(C_DIM / 128, N_TOK / 128), 256>>>(nullptr, Wproj, bproj,
                                                          out, C_DIM);
}

// round 2
// speedup vs baseline: 1.9742x; 1.9742x over previous
#include <cuda_runtime.h>
#include <math.h>

#define S_FR   16
#define P_TOK  512
#define C_DIM  768
#define H_HEADS 12
#define K_COV  6
#define D_DIM  64
#define N_TOK  8192
#define QKV_N  2304

// Scratch (allocation-free: __device__ globals)
__device__ float g_q[H_HEADS * N_TOK * D_DIM];
__device__ float g_k[H_HEADS * N_TOK * D_DIM];
__device__ float g_v[H_HEADS * N_TOK * D_DIM];
__device__ float g_attn[N_TOK * C_DIM];

// ---------------------------------------------------------------------------
// Tiled fp32 GEMM (unchanged from round 1): C = A[M,768]*B[768,N] + bias
// ---------------------------------------------------------------------------
template <int MODE>
__global__ __launch_bounds__(256) void gemm_kernel(
    const float* __restrict__ A, const float* __restrict__ B,
    const float* __restrict__ bias, float* __restrict__ Cout, int Ncols) {
  constexpr int BM = 128, BN = 128, BK = 16, TM = 8, TN = 8;
  __shared__ float As[BK][BM + 4];
  __shared__ float Bs[BK][BN];
  const int K = C_DIM;
  const int bn = blockIdx.x, bm = blockIdx.y;
  const int tid = threadIdx.x;
  const int tr = tid >> 4, tc = tid & 15;

  const float* Ap = (MODE == 1) ? (const float*)g_attn : A;

  float acc[TM][TN];
#pragma unroll
  for (int i = 0; i < TM; i++)
#pragma unroll
    for (int j = 0; j < TN; j++) acc[i][j] = 0.f;

  const int arow = tid >> 2;
  const int acol = (tid & 3) << 2;
  const int brow = tid >> 5;
  const int bcol = (tid & 31) << 2;

  const float* Ab = Ap + (size_t)(bm * BM) * K;
  const float* Bb = B + bn * BN;

  for (int k0 = 0; k0 < K; k0 += BK) {
#pragma unroll
    for (int i = 0; i < BM; i += 64) {
      float4 a = *(const float4*)&Ab[(size_t)(arow + i) * K + k0 + acol];
      As[acol + 0][arow + i] = a.x;
      As[acol + 1][arow + i] = a.y;
      As[acol + 2][arow + i] = a.z;
      As[acol + 3][arow + i] = a.w;
    }
#pragma unroll
    for (int i = 0; i < BK; i += 8) {
      *(float4*)&Bs[brow + i][bcol] =
          *(const float4*)&Bb[(size_t)(k0 + brow + i) * Ncols + bcol];
    }
    __syncthreads();
#pragma unroll
    for (int kk = 0; kk < BK; kk++) {
      float a[TM], b[TN];
      *(float4*)&a[0] = *(float4*)&As[kk][tr * TM + 0];
      *(float4*)&a[4] = *(float4*)&As[kk][tr * TM + 4];
      *(float4*)&b[0] = *(float4*)&Bs[kk][tc * TN + 0];
      *(float4*)&b[4] = *(float4*)&Bs[kk][tc * TN + 4];
#pragma unroll
      for (int i = 0; i < TM; i++)
#pragma unroll
        for (int j = 0; j < TN; j++) acc[i][j] = fmaf(a[i], b[j], acc[i][j]);
    }
    __syncthreads();
  }

#pragma unroll
  for (int i = 0; i < TM; i++) {
    const int row = bm * BM + tr * TM + i;
#pragma unroll
    for (int j = 0; j < TN; j++) {
      const int col = bn * BN + tc * TN + j;
      float v = acc[i][j] + bias[col];
      if (MODE == 0) {
        const int which = col / C_DIM;
        const int rem = col - which * C_DIM;
        const int h = rem >> 6, d = rem & 63;
        float* dst = (which == 0) ? g_q : (which == 1 ? g_k : g_v);
        dst[((size_t)h * N_TOK + row) * D_DIM + d] = v;
      } else {
        Cout[(size_t)row * C_DIM + col] = v;
      }
    }
  }
}

// ---------------------------------------------------------------------------
// TF32 mma flash attention.
// Block = (128-query tile, head, frame), 8 warps; each warp owns 16 q-rows.
// Key tiles of 64 streamed (48 tiles = 6 frames x 512).
// mma.sync.m16n8k8 tf32 for both QK^T and PV; online softmax in registers.
// ---------------------------------------------------------------------------
#define QST 68   // Qs/Ps stride (conflict-free a-fragment loads)
#define KST 72   // Ks/Vs stride
#define ATTN_SMEM ((128 * QST + 64 * KST + 64 * KST + 128 * QST) * 4)

__device__ __forceinline__ unsigned f2tf(float f) {
  unsigned u;
  asm("cvt.rna.tf32.f32 %0, %1;" : "=r"(u) : "f"(f));
  return u;
}
__device__ __forceinline__ float ex2(float x) {
  float y;
  asm("ex2.approx.ftz.f32 %0, %1;" : "=f"(y) : "f"(x));
  return y;
}
__device__ __forceinline__ void mma8(float c[4], const unsigned a[4],
                                     const unsigned b[2]) {
  asm volatile(
      "mma.sync.aligned.m16n8k8.row.col.f32.tf32.tf32.f32 "
      "{%0,%1,%2,%3},{%4,%5,%6,%7},{%8,%9},{%0,%1,%2,%3};\n"
      : "+f"(c[0]), "+f"(c[1]), "+f"(c[2]), "+f"(c[3])
      : "r"(a[0]), "r"(a[1]), "r"(a[2]), "r"(a[3]), "r"(b[0]), "r"(b[1]));
}

__global__ __launch_bounds__(256, 2) void attn_kernel(
    const int* __restrict__ covis) {
  extern __shared__ unsigned sm[];
  unsigned* Qs = sm;                    // [128][QST]
  unsigned* Ks = Qs + 128 * QST;        // [64][KST]  key-major
  unsigned* Vs = Ks + 64 * KST;         // [64][KST]  key-major
  unsigned* Ps = Vs + 64 * KST;         // [128][QST] per-warp-private slices

  const int tid = threadIdx.x;
  const int warp = tid >> 5, lane = tid & 31;
  const int gid = lane >> 2, tig = lane & 3;
  const int qt = blockIdx.x, h = blockIdx.y, f = blockIdx.z;

  // Stage Q tile (fp32 -> tf32)
  const float* qptr = g_q + ((size_t)h * N_TOK + f * P_TOK + qt * 128) * D_DIM;
#pragma unroll
  for (int j = 0; j < 8; j++) {
    int i = j * 256 + tid;
    int row = i >> 4, c4 = (i & 15) << 2;
    float4 qv = *(const float4*)&qptr[row * D_DIM + c4];
    uint4 t;
    t.x = f2tf(qv.x); t.y = f2tf(qv.y); t.z = f2tf(qv.z); t.w = f2tf(qv.w);
    *(uint4*)&Qs[row * QST + c4] = t;
  }

  float o[8][4];
#pragma unroll
  for (int nb = 0; nb < 8; nb++)
#pragma unroll
    for (int j = 0; j < 4; j++) o[nb][j] = 0.f;
  float m0 = -INFINITY, m1 = -INFINITY, l0 = 0.f, l1 = 0.f;
  const float CS = 0.18033688011f;  // 0.125 * log2(e)

  const unsigned* Qw = Qs + warp * 16 * QST;
  unsigned* Pw = Ps + warp * 16 * QST;

  for (int t = 0; t < (K_COV * P_TOK) / 64; t++) {
    const int frame = covis[f * K_COV + (t >> 3)];
    const int off = (t & 7) << 6;
    const float* kp =
        g_k + ((size_t)h * N_TOK + frame * P_TOK + off) * D_DIM;
    const float* vp =
        g_v + ((size_t)h * N_TOK + frame * P_TOK + off) * D_DIM;

    __syncthreads();  // previous tile's reads of Ks/Vs done
#pragma unroll
    for (int j = 0; j < 4; j++) {
      int i = j * 256 + tid;
      int key = i >> 4, c4 = (i & 15) << 2;
      float4 kv = *(const float4*)&kp[key * D_DIM + c4];
      float4 vv = *(const float4*)&vp[key * D_DIM + c4];
      uint4 a, b;
      a.x = f2tf(kv.x); a.y = f2tf(kv.y); a.z = f2tf(kv.z); a.w = f2tf(kv.w);
      b.x = f2tf(vv.x); b.y = f2tf(vv.y); b.z = f2tf(vv.z); b.w = f2tf(vv.w);
      *(uint4*)&Ks[key * KST + c4] = a;
      *(uint4*)&Vs[key * KST + c4] = b;
    }
    __syncthreads();

    // ---- S = Q K^T (warp computes 16x64) ----
    float s[8][4];
#pragma unroll
    for (int nb = 0; nb < 8; nb++)
#pragma unroll
      for (int j = 0; j < 4; j++) s[nb][j] = 0.f;
#pragma unroll
    for (int ks = 0; ks < 8; ks++) {
      unsigned a[4];
      a[0] = Qw[gid * QST + ks * 8 + tig];
      a[1] = Qw[(gid + 8) * QST + ks * 8 + tig];
      a[2] = Qw[gid * QST + ks * 8 + tig + 4];
      a[3] = Qw[(gid + 8) * QST + ks * 8 + tig + 4];
#pragma unroll
      for (int nb = 0; nb < 8; nb++) {
        unsigned b[2];
        b[0] = Ks[(nb * 8 + gid) * KST + ks * 8 + tig];
        b[1] = Ks[(nb * 8 + gid) * KST + ks * 8 + tig + 4];
        mma8(s[nb], a, b);
      }
    }

    // ---- online softmax (rows gid and gid+8 of this warp's 16) ----
    float mx0 = -INFINITY, mx1 = -INFINITY;
#pragma unroll
    for (int nb = 0; nb < 8; nb++) {
      mx0 = fmaxf(mx0, fmaxf(s[nb][0], s[nb][1]));
      mx1 = fmaxf(mx1, fmaxf(s[nb][2], s[nb][3]));
    }
    mx0 = fmaxf(mx0, __shfl_xor_sync(0xffffffffu, mx0, 1));
    mx0 = fmaxf(mx0, __shfl_xor_sync(0xffffffffu, mx0, 2));
    mx1 = fmaxf(mx1, __shfl_xor_sync(0xffffffffu, mx1, 1));
    mx1 = fmaxf(mx1, __shfl_xor_sync(0xffffffffu, mx1, 2));
    const float nm0 = fmaxf(m0, mx0), nm1 = fmaxf(m1, mx1);
    const float rf0 = ex2((m0 - nm0) * CS), rf1 = ex2((m1 - nm1) * CS);
    m0 = nm0; m1 = nm1;

    float sum0 = 0.f, sum1 = 0.f;
#pragma unroll
    for (int nb = 0; nb < 8; nb++) {
      float p0 = ex2((s[nb][0] - m0) * CS);
      float p1 = ex2((s[nb][1] - m0) * CS);
      float p2 = ex2((s[nb][2] - m1) * CS);
      float p3 = ex2((s[nb][3] - m1) * CS);
      sum0 += p0 + p1;
      sum1 += p2 + p3;
      uint2 u01; u01.x = f2tf(p0); u01.y = f2tf(p1);
      uint2 u23; u23.x = f2tf(p2); u23.y = f2tf(p3);
      *(uint2*)&Pw[gid * QST + nb * 8 + 2 * tig] = u01;
      *(uint2*)&Pw[(gid + 8) * QST + nb * 8 + 2 * tig] = u23;
    }
    sum0 += __shfl_xor_sync(0xffffffffu, sum0, 1);
    sum0 += __shfl_xor_sync(0xffffffffu, sum0, 2);
    sum1 += __shfl_xor_sync(0xffffffffu, sum1, 1);
    sum1 += __shfl_xor_sync(0xffffffffu, sum1, 2);
    l0 = l0 * rf0 + sum0;
    l1 = l1 * rf1 + sum1;
#pragma unroll
    for (int nb = 0; nb < 8; nb++) {
      o[nb][0] *= rf0; o[nb][1] *= rf0;
      o[nb][2] *= rf1; o[nb][3] *= rf1;
    }
    __syncwarp();  // P visible across the warp

    // ---- O += P V ----
#pragma unroll
    for (int ks = 0; ks < 8; ks++) {
      unsigned a[4];
      a[0] = Pw[gid * QST + ks * 8 + tig];
      a[1] = Pw[(gid + 8) * QST + ks * 8 + tig];
      a[2] = Pw[gid * QST + ks * 8 + tig + 4];
      a[3] = Pw[(gid + 8) * QST + ks * 8 + tig + 4];
#pragma unroll
      for (int nb = 0; nb < 8; nb++) {
        unsigned b[2];
        b[0] = Vs[(ks * 8 + tig) * KST + nb * 8 + gid];
        b[1] = Vs[(ks * 8 + tig + 4) * KST + nb * 8 + gid];
        mma8(o[nb], a, b);
      }
    }
    __syncwarp();  // P reads done before next tile's stores
  }

  // ---- finalize: O / l, write [N, H*D] ----
  const float inv0 = 1.f / l0, inv1 = 1.f / l1;
  const int tok0 = f * P_TOK + qt * 128 + warp * 16 + gid;
  float* op0 = g_attn + (size_t)tok0 * C_DIM + h * D_DIM;
  float* op1 = op0 + 8 * C_DIM;
#pragma unroll
  for (int nb = 0; nb < 8; nb++) {
    float2 w0, w1;
    w0.x = o[nb][0] * inv0; w0.y = o[nb][1] * inv0;
    w1.x = o[nb][2] * inv1; w1.y = o[nb][3] * inv1;
    *(float2*)&op0[nb * 8 + 2 * tig] = w0;
    *(float2*)&op1[nb * 8 + 2 * tig] = w1;
  }
}

// ---------------------------------------------------------------------------
extern "C" void kernel_launch(void* const* d_in, const int* in_sizes, int n_in,
                              void* d_out, int out_size) {
  const float* x     = (const float*)d_in[0];
  const float* Wqkv  = (const float*)d_in[1];
  const float* bqkv  = (const float*)d_in[2];
  const float* Wproj = (const float*)d_in[3];
  const float* bproj = (const float*)d_in[4];
  const int*   covis = (const int*)d_in[5];
  float* out = (float*)d_out;
  (void)in_sizes; (void)n_in; (void)out_size;

  cudaFuncSetAttribute(attn_kernel, cudaFuncAttributeMaxDynamicSharedMemorySize,
                       ATTN_SMEM);

  gemm_kernel<0><<<dim3(QKV_N / 128, N_TOK / 128), 256>>>(x, Wqkv, bqkv,
                                                          nullptr, QKV_N);
  attn_kernel<<<dim3(P_TOK / 128, H_HEADS, S_FR), 256, ATTN_SMEM>>>(covis);
  gemm_kernel<1><<<dim3(C_DIM / 128, N_TOK / 128), 256>>>(nullptr, Wproj, bproj,
                                                          out, C_DIM);
}

// round 3
// speedup vs baseline: 3.0617x; 1.5509x over previous
#include <cuda_runtime.h>
#include <math.h>

#define S_FR   16
#define P_TOK  512
#define C_DIM  768
#define H_HEADS 12
#define K_COV  6
#define D_DIM  64
#define N_TOK  8192
#define QKV_N  2304

// Scratch (allocation-free: __device__ globals)
__device__ float g_q[H_HEADS * N_TOK * D_DIM];
__device__ float g_k[H_HEADS * N_TOK * D_DIM];
__device__ float g_v[H_HEADS * N_TOK * D_DIM];
__device__ float g_attn[N_TOK * C_DIM];

__device__ __forceinline__ unsigned f2tf(float f) {
  unsigned u;
  asm("cvt.rna.tf32.f32 %0, %1;" : "=r"(u) : "f"(f));
  return u;
}
__device__ __forceinline__ float ex2(float x) {
  float y;
  asm("ex2.approx.ftz.f32 %0, %1;" : "=f"(y) : "f"(x));
  return y;
}
__device__ __forceinline__ void mma8(float c[4], const unsigned a[4],
                                     const unsigned b[2]) {
  asm volatile(
      "mma.sync.aligned.m16n8k8.row.col.f32.tf32.tf32.f32 "
      "{%0,%1,%2,%3},{%4,%5,%6,%7},{%8,%9},{%0,%1,%2,%3};\n"
      : "+f"(c[0]), "+f"(c[1]), "+f"(c[2]), "+f"(c[3])
      : "r"(a[0]), "r"(a[1]), "r"(a[2]), "r"(a[3]), "r"(b[0]), "r"(b[1]));
}
__device__ __forceinline__ uint4 tf4(float4 v) {
  uint4 t;
  t.x = f2tf(v.x); t.y = f2tf(v.y); t.z = f2tf(v.z); t.w = f2tf(v.w);
  return t;
}

// ---------------------------------------------------------------------------
// TF32 mma GEMM: C[M,Ncols] = A[M,768] * B[768,Ncols] + bias
// MODE 0: scatter into q/k/v [H,N,D];  MODE 1: A := g_attn, write d_out.
// BM=BN=128, BK=16, 8 warps (2x4), warp tile 64x32 = 16 m16n8k8 mma tiles.
// As [m][k] stride 20 (conflict-free a-frag loads), Bs [k][n] stride 136.
// ---------------------------------------------------------------------------
#define AST 20
#define BST 136

template <int MODE>
__global__ __launch_bounds__(256) void gemm_mma(
    const float* __restrict__ A, const float* __restrict__ B,
    const float* __restrict__ bias, float* __restrict__ Cout, int Ncols) {
  __shared__ unsigned As[128 * AST];
  __shared__ unsigned Bs[16 * BST];
  const int tid = threadIdx.x;
  const int warp = tid >> 5, lane = tid & 31;
  const int gid = lane >> 2, tig = lane & 3;
  const int wm = warp >> 2, wn = warp & 3;  // 2 x 4 warp grid
  const int bn = blockIdx.x, bm = blockIdx.y;

  const float* Ap = (MODE == 1) ? (const float*)g_attn : A;
  const float* Ab = Ap + (size_t)(bm * 128) * C_DIM;
  const float* Bb = B + bn * 128;

  const int arow = tid >> 2, acol = (tid & 3) << 2;   // A: 128 rows x 16 k
  const int brow = tid >> 5, bcol = (tid & 31) << 2;  // B: 16 k x 128 n

  float acc[16][4];
#pragma unroll
  for (int i = 0; i < 16; i++)
#pragma unroll
    for (int j = 0; j < 4; j++) acc[i][j] = 0.f;

  float4 pa0, pa1, pb0, pb1;
  pa0 = *(const float4*)&Ab[(size_t)arow * C_DIM + acol];
  pa1 = *(const float4*)&Ab[(size_t)(arow + 64) * C_DIM + acol];
  pb0 = *(const float4*)&Bb[(size_t)brow * Ncols + bcol];
  pb1 = *(const float4*)&Bb[(size_t)(brow + 8) * Ncols + bcol];

  const int NT = C_DIM / 16;  // 48 tiles
  for (int t = 0; t < NT; t++) {
    __syncthreads();  // previous tile's fragment reads done
    *(uint4*)&As[arow * AST + acol] = tf4(pa0);
    *(uint4*)&As[(arow + 64) * AST + acol] = tf4(pa1);
    *(uint4*)&Bs[brow * BST + bcol] = tf4(pb0);
    *(uint4*)&Bs[(brow + 8) * BST + bcol] = tf4(pb1);
    __syncthreads();

    if (t + 1 < NT) {
      const int k0 = (t + 1) * 16;
      pa0 = *(const float4*)&Ab[(size_t)arow * C_DIM + k0 + acol];
      pa1 = *(const float4*)&Ab[(size_t)(arow + 64) * C_DIM + k0 + acol];
      pb0 = *(const float4*)&Bb[(size_t)(k0 + brow) * Ncols + bcol];
      pb1 = *(const float4*)&Bb[(size_t)(k0 + brow + 8) * Ncols + bcol];
    }

#pragma unroll
    for (int ks = 0; ks < 2; ks++) {
      const int k = ks * 8;
      unsigned af[4][4], bf[4][2];
#pragma unroll
      for (int mt = 0; mt < 4; mt++) {
        const int m = wm * 64 + mt * 16 + gid;
        af[mt][0] = As[m * AST + k + tig];
        af[mt][1] = As[(m + 8) * AST + k + tig];
        af[mt][2] = As[m * AST + k + tig + 4];
        af[mt][3] = As[(m + 8) * AST + k + tig + 4];
      }
#pragma unroll
      for (int nt = 0; nt < 4; nt++) {
        const int n = wn * 32 + nt * 8 + gid;
        bf[nt][0] = Bs[(k + tig) * BST + n];
        bf[nt][1] = Bs[(k + tig + 4) * BST + n];
      }
#pragma unroll
      for (int mt = 0; mt < 4; mt++)
#pragma unroll
        for (int nt = 0; nt < 4; nt++) mma8(acc[mt * 4 + nt], af[mt], bf[nt]);
    }
  }

  // Epilogue: bias add + store (c-frag: rows gid/gid+8, cols 2*tig, 2*tig+1)
#pragma unroll
  for (int mt = 0; mt < 4; mt++) {
#pragma unroll
    for (int nt = 0; nt < 4; nt++) {
      const int row = bm * 128 + wm * 64 + mt * 16 + gid;
      const int col = bn * 128 + wn * 32 + nt * 8 + 2 * tig;
      const float b0 = bias[col], b1 = bias[col + 1];
      float2 lo, hi;
      lo.x = acc[mt * 4 + nt][0] + b0;
      lo.y = acc[mt * 4 + nt][1] + b1;
      hi.x = acc[mt * 4 + nt][2] + b0;
      hi.y = acc[mt * 4 + nt][3] + b1;
      if (MODE == 0) {
        const int which = col / C_DIM;  // uniform per 8-col group
        const int rem = col - which * C_DIM;
        const int h = rem >> 6, d = rem & 63;
        float* dst = (which == 0) ? g_q : (which == 1 ? g_k : g_v);
        *(float2*)&dst[((size_t)h * N_TOK + row) * D_DIM + d] = lo;
        *(float2*)&dst[((size_t)h * N_TOK + row + 8) * D_DIM + d] = hi;
      } else {
        *(float2*)&Cout[(size_t)row * C_DIM + col] = lo;
        *(float2*)&Cout[(size_t)(row + 8) * C_DIM + col] = hi;
      }
    }
  }
}

// ---------------------------------------------------------------------------
// TF32 mma flash attention (unchanged from round 2).
// ---------------------------------------------------------------------------
#define QST 68
#define KST 72
#define ATTN_SMEM ((128 * QST + 64 * KST + 64 * KST + 128 * QST) * 4)

__global__ __launch_bounds__(256, 2) void attn_kernel(
    const int* __restrict__ covis) {
  extern __shared__ unsigned sm[];
  unsigned* Qs = sm;
  unsigned* Ks = Qs + 128 * QST;
  unsigned* Vs = Ks + 64 * KST;
  unsigned* Ps = Vs + 64 * KST;

  const int tid = threadIdx.x;
  const int warp = tid >> 5, lane = tid & 31;
  const int gid = lane >> 2, tig = lane & 3;
  const int qt = blockIdx.x, h = blockIdx.y, f = blockIdx.z;

  const float* qptr = g_q + ((size_t)h * N_TOK + f * P_TOK + qt * 128) * D_DIM;
#pragma unroll
  for (int j = 0; j < 8; j++) {
    int i = j * 256 + tid;
    int row = i >> 4, c4 = (i & 15) << 2;
    *(uint4*)&Qs[row * QST + c4] = tf4(*(const float4*)&qptr[row * D_DIM + c4]);
  }

  float o[8][4];
#pragma unroll
  for (int nb = 0; nb < 8; nb++)
#pragma unroll
    for (int j = 0; j < 4; j++) o[nb][j] = 0.f;
  float m0 = -INFINITY, m1 = -INFINITY, l0 = 0.f, l1 = 0.f;
  const float CS = 0.18033688011f;  // 0.125 * log2(e)

  const unsigned* Qw = Qs + warp * 16 * QST;
  unsigned* Pw = Ps + warp * 16 * QST;

  for (int t = 0; t < (K_COV * P_TOK) / 64; t++) {
    const int frame = covis[f * K_COV + (t >> 3)];
    const int off = (t & 7) << 6;
    const float* kp = g_k + ((size_t)h * N_TOK + frame * P_TOK + off) * D_DIM;
    const float* vp = g_v + ((size_t)h * N_TOK + frame * P_TOK + off) * D_DIM;

    __syncthreads();
#pragma unroll
    for (int j = 0; j < 4; j++) {
      int i = j * 256 + tid;
      int key = i >> 4, c4 = (i & 15) << 2;
      *(uint4*)&Ks[key * KST + c4] = tf4(*(const float4*)&kp[key * D_DIM + c4]);
      *(uint4*)&Vs[key * KST + c4] = tf4(*(const float4*)&vp[key * D_DIM + c4]);
    }
    __syncthreads();

    float s[8][4];
#pragma unroll
    for (int nb = 0; nb < 8; nb++)
#pragma unroll
      for (int j = 0; j < 4; j++) s[nb][j] = 0.f;
#pragma unroll
    for (int ks = 0; ks < 8; ks++) {
      unsigned a[4];
      a[0] = Qw[gid * QST + ks * 8 + tig];
      a[1] = Qw[(gid + 8) * QST + ks * 8 + tig];
      a[2] = Qw[gid * QST + ks * 8 + tig + 4];
      a[3] = Qw[(gid + 8) * QST + ks * 8 + tig + 4];
#pragma unroll
      for (int nb = 0; nb < 8; nb++) {
        unsigned b[2];
        b[0] = Ks[(nb * 8 + gid) * KST + ks * 8 + tig];
        b[1] = Ks[(nb * 8 + gid) * KST + ks * 8 + tig + 4];
        mma8(s[nb], a, b);
      }
    }

    float mx0 = -INFINITY, mx1 = -INFINITY;
#pragma unroll
    for (int nb = 0; nb < 8; nb++) {
      mx0 = fmaxf(mx0, fmaxf(s[nb][0], s[nb][1]));
      mx1 = fmaxf(mx1, fmaxf(s[nb][2], s[nb][3]));
    }
    mx0 = fmaxf(mx0, __shfl_xor_sync(0xffffffffu, mx0, 1));
    mx0 = fmaxf(mx0, __shfl_xor_sync(0xffffffffu, mx0, 2));
    mx1 = fmaxf(mx1, __shfl_xor_sync(0xffffffffu, mx1, 1));
    mx1 = fmaxf(mx1, __shfl_xor_sync(0xffffffffu, mx1, 2));
    const float nm0 = fmaxf(m0, mx0), nm1 = fmaxf(m1, mx1);
    const float rf0 = ex2((m0 - nm0) * CS), rf1 = ex2((m1 - nm1) * CS);
    m0 = nm0; m1 = nm1;

    float sum0 = 0.f, sum1 = 0.f;
#pragma unroll
    for (int nb = 0; nb < 8; nb++) {
      float p0 = ex2((s[nb][0] - m0) * CS);
      float p1 = ex2((s[nb][1] - m0) * CS);
      float p2 = ex2((s[nb][2] - m1) * CS);
      float p3 = ex2((s[nb][3] - m1) * CS);
      sum0 += p0 + p1;
      sum1 += p2 + p3;
      uint2 u01; u01.x = f2tf(p0); u01.y = f2tf(p1);
      uint2 u23; u23.x = f2tf(p2); u23.y = f2tf(p3);
      *(uint2*)&Pw[gid * QST + nb * 8 + 2 * tig] = u01;
      *(uint2*)&Pw[(gid + 8) * QST + nb * 8 + 2 * tig] = u23;
    }
    sum0 += __shfl_xor_sync(0xffffffffu, sum0, 1);
    sum0 += __shfl_xor_sync(0xffffffffu, sum0, 2);
    sum1 += __shfl_xor_sync(0xffffffffu, sum1, 1);
    sum1 += __shfl_xor_sync(0xffffffffu, sum1, 2);
    l0 = l0 * rf0 + sum0;
    l1 = l1 * rf1 + sum1;
#pragma unroll
    for (int nb = 0; nb < 8; nb++) {
      o[nb][0] *= rf0; o[nb][1] *= rf0;
      o[nb][2] *= rf1; o[nb][3] *= rf1;
    }
    __syncwarp();

#pragma unroll
    for (int ks = 0; ks < 8; ks++) {
      unsigned a[4];
      a[0] = Pw[gid * QST + ks * 8 + tig];
      a[1] = Pw[(gid + 8) * QST + ks * 8 + tig];
      a[2] = Pw[gid * QST + ks * 8 + tig + 4];
      a[3] = Pw[(gid + 8) * QST + ks * 8 + tig + 4];
#pragma unroll
      for (int nb = 0; nb < 8; nb++) {
        unsigned b[2];
        b[0] = Vs[(ks * 8 + tig) * KST + nb * 8 + gid];
        b[1] = Vs[(ks * 8 + tig + 4) * KST + nb * 8 + gid];
        mma8(o[nb], a, b);
      }
    }
    __syncwarp();
  }

  const float inv0 = 1.f / l0, inv1 = 1.f / l1;
  const int tok0 = f * P_TOK + qt * 128 + warp * 16 + gid;
  float* op0 = g_attn + (size_t)tok0 * C_DIM + h * D_DIM;
  float* op1 = op0 + 8 * C_DIM;
#pragma unroll
  for (int nb = 0; nb < 8; nb++) {
    float2 w0, w1;
    w0.x = o[nb][0] * inv0; w0.y = o[nb][1] * inv0;
    w1.x = o[nb][2] * inv1; w1.y = o[nb][3] * inv1;
    *(float2*)&op0[nb * 8 + 2 * tig] = w0;
    *(float2*)&op1[nb * 8 + 2 * tig] = w1;
  }
}

// ---------------------------------------------------------------------------
extern "C" void kernel_launch(void* const* d_in, const int* in_sizes, int n_in,
                              void* d_out, int out_size) {
  const float* x     = (const float*)d_in[0];
  const float* Wqkv  = (const float*)d_in[1];
  const float* bqkv  = (const float*)d_in[2];
  const float* Wproj = (const float*)d_in[3];
  const float* bproj = (const float*)d_in[4];
  const int*   covis = (const int*)d_in[5];
  float* out = (float*)d_out;
  (void)in_sizes; (void)n_in; (void)out_size;

  cudaFuncSetAttribute(attn_kernel, cudaFuncAttributeMaxDynamicSharedMemorySize,
                       ATTN_SMEM);

  gemm_mma<0><<<dim3(QKV_N / 128, N_TOK / 128), 256>>>(x, Wqkv, bqkv,
                                                       nullptr, QKV_N);
  attn_kernel<<<dim3(P_TOK / 128, H_HEADS, S_FR), 256, ATTN_SMEM>>>(covis);
  gemm_mma<1><<<dim3(C_DIM / 128, N_TOK / 128), 256>>>(nullptr, Wproj, bproj,
                                                       out, C_DIM);
}